// round 1
// baseline (speedup 1.0000x reference)
#include <cuda_runtime.h>

#define T_OBS 8
#define T_PRE 12
#define BATCH 524288
#define INP 2
#define EMB 16
#define H 8
#define G4 32  // 4*H

// Folded weights per phase: gates = A0*x0 + A1*x1 + b + Whh^T h
// Whh stored k-major: Whh[k][j] = W_hh[j, k] so unrolled j-loops vectorize.
struct Prep {
    float A0[G4];
    float A1[G4];
    float b[G4];
    float Whh[H][G4];
};

__device__ Prep g_prep[2];

__global__ void prep_kernel(const float* __restrict__ W_in, const float* __restrict__ b_in,
                            const float* __restrict__ W_ih_obs, const float* __restrict__ W_hh_obs,
                            const float* __restrict__ b_ih_obs, const float* __restrict__ b_hh_obs,
                            const float* __restrict__ W_ih_pre, const float* __restrict__ W_hh_pre,
                            const float* __restrict__ b_ih_pre, const float* __restrict__ b_hh_pre) {
    int j = threadIdx.x;   // 0..31  (gate row)
    int p = threadIdx.y;   // 0..1   (phase: 0=obs, 1=pre)
    const float* W_ih = p ? W_ih_pre : W_ih_obs;
    const float* W_hh = p ? W_hh_pre : W_hh_obs;
    const float* b_ih = p ? b_ih_pre : b_ih_obs;
    const float* b_hh = p ? b_hh_pre : b_hh_obs;

    float a0 = 0.f, a1 = 0.f, bb = 0.f;
#pragma unroll
    for (int e = 0; e < EMB; e++) {
        float w = W_ih[j * EMB + e];
        a0 = fmaf(w, W_in[e * INP + 0], a0);
        a1 = fmaf(w, W_in[e * INP + 1], a1);
        bb = fmaf(w, b_in[e], bb);
    }
    g_prep[p].A0[j] = a0;
    g_prep[p].A1[j] = a1;
    g_prep[p].b[j]  = bb + b_ih[j] + b_hh[j];
#pragma unroll
    for (int k = 0; k < H; k++)
        g_prep[p].Whh[k][j] = W_hh[j * H + k];
}

__device__ __forceinline__ float sigf(float x) {
    // 1/(1+exp(-x)) : MUFU.EX2 + MUFU.RCP, ~1e-6 rel err
    return __fdividef(1.0f, 1.0f + __expf(-x));
}
__device__ __forceinline__ float tanhfast(float x) {
    // tanh(x) = 2*sigmoid(2x) - 1
    return fmaf(2.0f, sigf(2.0f * x), -1.0f);
}

template <int T>
__device__ __forceinline__ void lstm_scan(const float* __restrict__ xin, int b,
                                          const Prep* __restrict__ P,
                                          float h[H], float c[H]) {
#pragma unroll 1
    for (int t = 0; t < T; t++) {
        float2 x = *(const float2*)(xin + ((size_t)t * BATCH + b) * INP);
        float g[G4];
#pragma unroll
        for (int j = 0; j < G4; j++)
            g[j] = fmaf(P->A1[j], x.y, fmaf(P->A0[j], x.x, P->b[j]));
#pragma unroll
        for (int k = 0; k < H; k++) {
            float hk = h[k];
#pragma unroll
            for (int j = 0; j < G4; j++)
                g[j] = fmaf(P->Whh[k][j], hk, g[j]);
        }
#pragma unroll
        for (int k = 0; k < H; k++) {
            float ig = sigf(g[k]);
            float fg = sigf(g[H + k]);
            float gg = tanhfast(g[2 * H + k]);
            float og = sigf(g[3 * H + k]);
            c[k] = fmaf(fg, c[k], ig * gg);
            h[k] = og * tanhfast(c[k]);
        }
    }
}

__global__ __launch_bounds__(256) void lstm_kernel(
    const float* __restrict__ obs, const float* __restrict__ pre,
    const float* __restrict__ h0, const float* __restrict__ c0,
    const float* __restrict__ c0p, float* __restrict__ out)
{
    __shared__ Prep sp[2];
    {
        const float* src = (const float*)g_prep;
        float* dst = (float*)sp;
        constexpr int NF = (int)(sizeof(Prep) * 2 / sizeof(float));
        for (int i = threadIdx.x; i < NF; i += 256) dst[i] = src[i];
    }
    __syncthreads();

    const int b = blockIdx.x * 256 + threadIdx.x;

    float h[H], c[H];
    {
        float4 a = *(const float4*)(h0 + (size_t)b * H);
        float4 d = *(const float4*)(h0 + (size_t)b * H + 4);
        h[0]=a.x; h[1]=a.y; h[2]=a.z; h[3]=a.w; h[4]=d.x; h[5]=d.y; h[6]=d.z; h[7]=d.w;
        a = *(const float4*)(c0 + (size_t)b * H);
        d = *(const float4*)(c0 + (size_t)b * H + 4);
        c[0]=a.x; c[1]=a.y; c[2]=a.z; c[3]=a.w; c[4]=d.x; c[5]=d.y; c[6]=d.z; c[7]=d.w;
    }

    // Phase 1: observation scan
    lstm_scan<T_OBS>(obs, b, &sp[0], h, c);

    // c_out = h.T flattened: out[j*B + b] = h[j]
#pragma unroll
    for (int j = 0; j < H; j++)
        out[(size_t)j * BATCH + b] = h[j];

    // Phase 2: prediction scan (h carries over, c reset to c0_pre)
    {
        float4 a = *(const float4*)(c0p + (size_t)b * H);
        float4 d = *(const float4*)(c0p + (size_t)b * H + 4);
        c[0]=a.x; c[1]=a.y; c[2]=a.z; c[3]=a.w; c[4]=d.x; c[5]=d.y; c[6]=d.z; c[7]=d.w;
    }
    lstm_scan<T_PRE>(pre, b, &sp[1], h, c);

#pragma unroll
    for (int j = 0; j < H; j++)
        out[(size_t)(H + j) * BATCH + b] = h[j];
}

extern "C" void kernel_launch(void* const* d_in, const int* in_sizes, int n_in,
                              void* d_out, int out_size) {
    const float* obs  = (const float*)d_in[0];
    const float* pre  = (const float*)d_in[1];
    const float* h0   = (const float*)d_in[2];
    const float* c0   = (const float*)d_in[3];
    const float* c0p  = (const float*)d_in[4];
    const float* W_in = (const float*)d_in[5];
    const float* b_in = (const float*)d_in[6];

    prep_kernel<<<1, dim3(32, 2)>>>(
        W_in, b_in,
        (const float*)d_in[7],  (const float*)d_in[8],
        (const float*)d_in[9],  (const float*)d_in[10],
        (const float*)d_in[11], (const float*)d_in[12],
        (const float*)d_in[13], (const float*)d_in[14]);

    lstm_kernel<<<BATCH / 256, 256>>>(obs, pre, h0, c0, c0p, (float*)d_out);
}